// round 15
// baseline (speedup 1.0000x reference)
#include <cuda_runtime.h>
#include <cuda_fp16.h>
#include <cstdint>

// ---------------------------------------------------------------------------
// SynapticPlasticityModule on GB300 — mma.sync fp16 GEMM (r4 config, exact),
// 4-launch graph: reduce_means eliminated (xmean in prep, omean/m in weights).
// Outputs (d_out, fp32): [output B*H][new_w H*H][new_meta H][hist ACT]
// ---------------------------------------------------------------------------

#define H_DIM 1024
#define B_DIM 16384
#define HIST_LEN 100
#define SPLITX 256
#define MTILES (B_DIM / 128)                // 128

#define TM 128
#define TN 128
#define KC 64
#define NCHUNK (H_DIM / KC)                 // 16
#define STAGE_BYTES (TM * 128 + TN * 128)   // 32768
#define GEMM_SMEM (2 * STAGE_BYTES)         // 65536

// __device__ scratch — g_xpart / g_opart stored TRANSPOSED [h][i] row-major.
__device__ __half g_xh[(size_t)B_DIM * H_DIM];
__device__ __half g_wh[(size_t)H_DIM * H_DIM];
__device__ float  g_xpart[H_DIM * SPLITX];
__device__ float  g_opart[H_DIM * MTILES];
__device__ float  g_ototal[1024];           // per-GEMM-CTA tile sums
__device__ float  g_xmean[H_DIM];
__device__ float  g_a[H_DIM];
__device__ float  g_b[H_DIM];               // history part only (w99*om added inline)

__device__ __forceinline__ uint32_t smem_u32(const void* p) {
    uint32_t a;
    asm("{ .reg .u64 t; cvta.to.shared.u64 t, %1; cvt.u32.u64 %0, t; }"
        : "=r"(a) : "l"(p));
    return a;
}
#define SW128(off) ((off) ^ (((off) >> 3) & 0x70))

#define CP_ASYNC16(smem_addr, gptr) \
    asm volatile("cp.async.cg.shared.global [%0], [%1], 16;" \
                 :: "r"(smem_addr), "l"(gptr) : "memory")
#define CP_COMMIT() asm volatile("cp.async.commit_group;" ::: "memory")
#define CP_WAIT1()  asm volatile("cp.async.wait_group 1;" ::: "memory")
#define CP_WAIT0()  asm volatile("cp.async.wait_group 0;" ::: "memory")

__device__ __forceinline__ void ldmx4(uint32_t* r, uint32_t addr) {
    asm volatile("ldmatrix.sync.aligned.m8n8.x4.shared.b16 {%0,%1,%2,%3}, [%4];"
                 : "=r"(r[0]), "=r"(r[1]), "=r"(r[2]), "=r"(r[3]) : "r"(addr));
}
__device__ __forceinline__ void mma16816(float* d, const uint32_t* a,
                                         const uint32_t* b) {
    asm volatile(
        "mma.sync.aligned.m16n8k16.row.col.f32.f16.f16.f32 "
        "{%0,%1,%2,%3}, {%4,%5,%6,%7}, {%8,%9}, {%0,%1,%2,%3};"
        : "+f"(d[0]), "+f"(d[1]), "+f"(d[2]), "+f"(d[3])
        : "r"(a[0]), "r"(a[1]), "r"(a[2]), "r"(a[3]), "r"(b[0]), "r"(b[1]));
}

// ---------------------------------------------------------------------------
// convert_x (r14 exact): fp32 -> fp16, transposed column partials.
// ---------------------------------------------------------------------------
__global__ __launch_bounds__(256) void convert_x(const float* __restrict__ x)
{
    const int rows_per = B_DIM / SPLITX;     // 64
    const int c4 = threadIdx.x * 4;
    const size_t row0 = (size_t)blockIdx.y * rows_per;

    float4 s = make_float4(0.f, 0.f, 0.f, 0.f);
    const float* p = x + row0 * H_DIM + c4;
    __half* q = g_xh + row0 * H_DIM + c4;

#pragma unroll 4
    for (int r = 0; r < rows_per; r++) {
        float4 v = *reinterpret_cast<const float4*>(p + (size_t)r * H_DIM);
        s.x += v.x; s.y += v.y; s.z += v.z; s.w += v.w;
        __half2 h01 = __floats2half2_rn(v.x, v.y);
        __half2 h23 = __floats2half2_rn(v.z, v.w);
        *reinterpret_cast<uint2*>(q + (size_t)r * H_DIM) =
            make_uint2(*reinterpret_cast<uint32_t*>(&h01),
                       *reinterpret_cast<uint32_t*>(&h23));
    }
    const int blk = blockIdx.y;
    g_xpart[(size_t)(c4 + 0) * SPLITX + blk] = s.x;
    g_xpart[(size_t)(c4 + 1) * SPLITX + blk] = s.y;
    g_xpart[(size_t)(c4 + 2) * SPLITX + blk] = s.z;
    g_xpart[(size_t)(c4 + 3) * SPLITX + blk] = s.w;
}

// ---------------------------------------------------------------------------
// prep_small: [0,1024) convert_w tiles; [1024,1152) STDP history sums;
// [1152,1280) xmean reduce (coalesced, warp-per-h; xpart ready — stream order).
// ---------------------------------------------------------------------------
__global__ __launch_bounds__(256) void prep_small(
    const float* __restrict__ W, const float* __restrict__ meta,
    const float* __restrict__ pre_hist, const float* __restrict__ post_hist,
    const float* __restrict__ d_win, const float* __restrict__ d_dec, float invB)
{
    __shared__ float tile[32][33];

    if (blockIdx.x < 1024) {
        const int wb = blockIdx.x;
        const int n0 = (wb & 31) * 32;
        const int k0 = (wb >> 5) * 32;
        const int tx = threadIdx.x & 31;
        const int ty = threadIdx.x >> 5;
#pragma unroll
        for (int i = ty; i < 32; i += 8)
            tile[i][tx] = W[(size_t)(k0 + i) * H_DIM + n0 + tx] * meta[n0 + tx];
        __syncthreads();
#pragma unroll
        for (int i = ty; i < 32; i += 8)
            g_wh[(size_t)(n0 + i) * H_DIM + k0 + tx] = __float2half_rn(tile[tx][i]);
    } else if (blockIdx.x < 1152) {
        const int wid  = threadIdx.x >> 5;
        const int lane = threadIdx.x & 31;
        const int h = (blockIdx.x - 1024) * 8 + wid;

        const float win = *d_win, dec = *d_dec;

        float a = 0.0f, b = 0.0f;
#pragma unroll
        for (int ii = 0; ii < 4; ii++) {
            int i = ii * 32 + lane;
            if (i < 99) {
                float dt = (float)(HIST_LEN - i) * win;
                float wv = 0.01f * expf(-dt * dec);
                a += wv * pre_hist[(size_t)(i + 1) * H_DIM + h];
                if (i >= 1) b += wv * post_hist[(size_t)(i + 1) * H_DIM + h];
            }
        }
#pragma unroll
        for (int o = 16; o > 0; o >>= 1) {
            a += __shfl_xor_sync(0xffffffffu, a, o);
            b += __shfl_xor_sync(0xffffffffu, b, o);
        }
        if (lane == 0) {
            g_a[h] = a;
            g_b[h] = b;
        }
    } else {
        const int wid  = threadIdx.x >> 5;
        const int lane = threadIdx.x & 31;
        const int h = (blockIdx.x - 1152) * 8 + wid;

        const float4* xp = reinterpret_cast<const float4*>(g_xpart + (size_t)h * SPLITX);
        float4 a0 = xp[lane];
        float4 a1 = xp[lane + 32];
        float sx = (a0.x + a0.y) + (a0.z + a0.w) + (a1.x + a1.y) + (a1.z + a1.w);
#pragma unroll
        for (int o = 16; o > 0; o >>= 1)
            sx += __shfl_xor_sync(0xffffffffu, sx, o);
        if (lane == 0) g_xmean[h] = sx * invB;
    }
}

// ---------------------------------------------------------------------------
// GEMM (r4 mainloop exact): transposed opart store + per-CTA total.
// ---------------------------------------------------------------------------
__global__ __launch_bounds__(256) void gemm_mma(float* __restrict__ C)
{
    extern __shared__ char smem[];
    const uint32_t sb = smem_u32(smem);
    const int tid  = threadIdx.x;
    const int wid  = tid >> 5;
    const int lane = tid & 31;
    const int m0 = blockIdx.y * TM;
    const int n0 = blockIdx.x * TN;
    const int m_w = (wid & 3) * 32;
    const int n_w = (wid >> 2) * 64;

    float acc[2][8][4];
#pragma unroll
    for (int i = 0; i < 2; i++)
#pragma unroll
        for (int j = 0; j < 8; j++)
#pragma unroll
            for (int q = 0; q < 4; q++) acc[i][j][q] = 0.0f;

    const int lrow = tid >> 3;
    const int lseg = tid & 7;
    const __half* gA = g_xh + (size_t)(m0 + lrow) * H_DIM + lseg * 8;
    const __half* gB = g_wh + (size_t)(n0 + lrow) * H_DIM + lseg * 8;

#define LOAD_STAGE(c, s) do {                                                  \
    const uint32_t base = sb + (s) * STAGE_BYTES;                              \
    const int koff = (c) * KC;                                                 \
    _Pragma("unroll")                                                          \
    for (int it = 0; it < 4; it++) {                                           \
        int row = it * 32 + lrow;                                              \
        uint32_t off = SW128((uint32_t)(row * 128 + lseg * 16));               \
        CP_ASYNC16(base + off, gA + (size_t)it * 32 * H_DIM + koff);           \
    }                                                                          \
    _Pragma("unroll")                                                          \
    for (int it = 0; it < 4; it++) {                                           \
        int row = it * 32 + lrow;                                              \
        uint32_t off = SW128((uint32_t)(row * 128 + lseg * 16));               \
        CP_ASYNC16(base + TM * 128 + off, gB + (size_t)it * 32 * H_DIM + koff);\
    }                                                                          \
} while (0)

    LOAD_STAGE(0, 0);
    CP_COMMIT();

    const int a_row = m_w + (lane & 15);
    const int a_colb = (lane >> 4) << 4;
    const int b_row = n_w + (lane & 7) + ((lane >> 4) & 1) * 8;
    const int b_colb = ((lane >> 3) & 1) << 4;

    for (int c = 0; c < NCHUNK; c++) {
        if (c + 1 < NCHUNK) {
            LOAD_STAGE(c + 1, (c + 1) & 1);
            CP_COMMIT();
            CP_WAIT1();
        } else {
            CP_WAIT0();
        }
        __syncthreads();

        const uint32_t baseA = sb + (c & 1) * STAGE_BYTES;
        const uint32_t baseB = baseA + TM * 128;

#pragma unroll
        for (int ks = 0; ks < KC / 16; ks++) {
            uint32_t a[2][4], b[4][4];
#pragma unroll
            for (int mi = 0; mi < 2; mi++) {
                uint32_t off = (uint32_t)((a_row + mi * 16) * 128 + ks * 32 + a_colb);
                ldmx4(a[mi], baseA + SW128(off));
            }
#pragma unroll
            for (int bq = 0; bq < 4; bq++) {
                uint32_t off = (uint32_t)((b_row + bq * 16) * 128 + ks * 32 + b_colb);
                ldmx4(b[bq], baseB + SW128(off));
            }
#pragma unroll
            for (int mi = 0; mi < 2; mi++)
#pragma unroll
                for (int bq = 0; bq < 4; bq++) {
                    mma16816(acc[mi][bq * 2 + 0], a[mi], &b[bq][0]);
                    mma16816(acc[mi][bq * 2 + 1], a[mi], &b[bq][2]);
                }
        }
        __syncthreads();
    }

    // ---- epilogue 1: store C tile
    const int g = lane >> 2, tig = lane & 3;
#pragma unroll
    for (int mi = 0; mi < 2; mi++) {
        const size_t r0 = (size_t)(m0 + m_w + mi * 16 + g);
#pragma unroll
        for (int ni = 0; ni < 8; ni++) {
            const int col = n0 + n_w + ni * 8 + tig * 2;
            *reinterpret_cast<float2*>(C + r0 * H_DIM + col) =
                make_float2(acc[mi][ni][0], acc[mi][ni][1]);
            *reinterpret_cast<float2*>(C + (r0 + 8) * H_DIM + col) =
                make_float2(acc[mi][ni][2], acc[mi][ni][3]);
        }
    }

    // ---- epilogue 2: fused column sums -> g_opart[h][mtile] + CTA total
    float* red = reinterpret_cast<float*>(smem);         // 512 floats
    float* tot = red + 512;                              // 4 floats
#pragma unroll
    for (int ni = 0; ni < 8; ni++) {
        float s0 = acc[0][ni][0] + acc[0][ni][2] + acc[1][ni][0] + acc[1][ni][2];
        float s1 = acc[0][ni][1] + acc[0][ni][3] + acc[1][ni][1] + acc[1][ni][3];
#pragma unroll
        for (int o = 4; o < 32; o <<= 1) {
            s0 += __shfl_xor_sync(0xffffffffu, s0, o);
            s1 += __shfl_xor_sync(0xffffffffu, s1, o);
        }
        if (lane < 4) {
            int col = n_w + ni * 8 + lane * 2;
            red[(wid & 3) * 128 + col]     = s0;
            red[(wid & 3) * 128 + col + 1] = s1;
        }
    }
    __syncthreads();
    float s = 0.0f;
    if (tid < 128) {
        s = red[tid] + red[128 + tid] + red[256 + tid] + red[384 + tid];
        g_opart[(size_t)(n0 + tid) * MTILES + blockIdx.y] = s;
#pragma unroll
        for (int o = 16; o > 0; o >>= 1)
            s += __shfl_xor_sync(0xffffffffu, s, o);
        if (lane == 0) tot[wid] = s;
    }
    __syncthreads();
    if (tid == 0)
        g_ototal[blockIdx.y * 8 + blockIdx.x] =
            (tot[0] + tot[1]) + (tot[2] + tot[3]);
#undef LOAD_STAGE
}

// ---------------------------------------------------------------------------
// weights + meta + scalars + hist. Each block = one weight row r = blockIdx.x.
// Computes m (from g_ototal), omean[r] (from transposed opart row), factor,
// and gb inline — reduce_means kernel eliminated.
// ---------------------------------------------------------------------------
__global__ __launch_bounds__(256) void weights_meta_kernel(
    const float* __restrict__ W, const float* __restrict__ meta,
    const float* __restrict__ act, const int* __restrict__ d_ptr,
    const float* __restrict__ d_target, const float* __restrict__ d_hrate,
    const float* __restrict__ d_mlr,
    const float* __restrict__ d_win, const float* __restrict__ d_dec,
    float* __restrict__ out_w, float* __restrict__ out_meta,
    float* __restrict__ out_hist, int act_len, float invB)
{
    __shared__ float sred[8];
    __shared__ float sbc[3];
    const int tid = threadIdx.x;
    const int wid = tid >> 5;
    const int lane = tid & 31;
    const int r = blockIdx.x;          // this block's weight row

    // ---- m = overall output mean, from per-CTA tile totals (1024 values)
    float pm = 0.0f;
#pragma unroll
    for (int i = tid; i < 1024; i += 256) pm += g_ototal[i];
#pragma unroll
    for (int o = 16; o > 0; o >>= 1) pm += __shfl_xor_sync(0xffffffffu, pm, o);
    if (lane == 0) sred[wid] = pm;
    __syncthreads();
    if (wid == 0) {
        float t = (lane < 8) ? sred[lane] : 0.0f;
#pragma unroll
        for (int o = 4; o > 0; o >>= 1) t += __shfl_xor_sync(0xffffffffu, t, o);
        if (lane == 0) sbc[0] = t * invB / (float)H_DIM;
    }
    __syncthreads();

    // ---- act sum
    float pa = 0.0f;
    for (int i = tid; i < act_len; i += 256) pa += act[i];
#pragma unroll
    for (int o = 16; o > 0; o >>= 1) pa += __shfl_xor_sync(0xffffffffu, pa, o);
    if (lane == 0) sred[wid] = pa;
    __syncthreads();
    if (wid == 0) {
        float t = (lane < 8) ? sred[lane] : 0.0f;
#pragma unroll
        for (int o = 4; o > 0; o >>= 1) t += __shfl_xor_sync(0xffffffffu, t, o);
        if (lane == 0) sbc[1] = t;
    }

    // ---- omean[r]: coalesced 128-float reduce of transposed opart row (warp 1)
    if (wid == 1) {
        float4 o4 = reinterpret_cast<const float4*>(g_opart + (size_t)r * MTILES)[lane];
        float so = (o4.x + o4.y) + (o4.z + o4.w);
#pragma unroll
        for (int o = 16; o > 0; o >>= 1) so += __shfl_xor_sync(0xffffffffu, so, o);
        if (lane == 0) sbc[2] = so * invB;
    }
    __syncthreads();

    const float m = sbc[0];
    const float om = sbc[2];
    const int ptr = *d_ptr;
    const float hist_mean = (sbc[1] - act[ptr] + m) / (float)act_len;
    const float factor = 1.0f + (*d_hrate) * ((*d_target) - hist_mean);
    const float w99 = 0.01f * expf(-(1.0f * (*d_win)) * (*d_dec));
    const float gb = g_b[r] + w99 * om;

    // ---- block 0 writes hist output
    if (blockIdx.x == 0) {
        for (int i = tid; i < act_len; i += 256)
            out_hist[i] = (i == ptr) ? m : act[i];
    }

    // ---- weight update (float4); base = r*1024 + tid*4
    size_t i4 = (size_t)blockIdx.x * 256 + tid;
    size_t base = i4 * 4;
    int c = (int)(base & (H_DIM - 1));

    float4 w  = *reinterpret_cast<const float4*>(W + base);
    float4 ga = *reinterpret_cast<const float4*>(g_a + c);
    float4 xm = *reinterpret_cast<const float4*>(g_xmean + c);

    float4 v;
    v.x = w.x + om * ga.x - gb * xm.x;
    v.y = w.y + om * ga.y - gb * xm.y;
    v.z = w.z + om * ga.z - gb * xm.z;
    v.w = w.w + om * ga.w - gb * xm.w;
#define CLIP1(t) t = fminf(fmaxf(t, -1.0f), 1.0f)
    CLIP1(v.x); CLIP1(v.y); CLIP1(v.z); CLIP1(v.w);
    v.x *= factor; v.y *= factor; v.z *= factor; v.w *= factor;
    CLIP1(v.x); CLIP1(v.y); CLIP1(v.z); CLIP1(v.w);
#undef CLIP1
    *reinterpret_cast<float4*>(out_w + base) = v;

    // ---- meta update (first H threads overall): own omean reduce
    if (i4 < H_DIM) {
        float so = 0.0f;
        const float* op = g_opart + i4 * MTILES;
#pragma unroll 4
        for (int k = 0; k < MTILES; k++) so += op[k];
        float omi = so * invB;
        float mlr = *d_mlr;
        float mv = meta[i4] + mlr * (omi - meta[i4]);
        out_meta[i4] = fminf(fmaxf(mv, 0.0f), 2.0f);
    }
}

// ---------------------------------------------------------------------------
extern "C" void kernel_launch(void* const* d_in, const int* in_sizes, int n_in,
                              void* d_out, int out_size)
{
    const float* x      = (const float*)d_in[0];
    const float* W      = (const float*)d_in[1];
    const float* meta   = (const float*)d_in[2];
    const float* pre    = (const float*)d_in[3];
    const float* post   = (const float*)d_in[4];
    const float* act    = (const float*)d_in[5];
    const int*   ptr    = (const int*)d_in[6];
    const float* win    = (const float*)d_in[7];
    const float* dec    = (const float*)d_in[8];
    const float* target = (const float*)d_in[9];
    const float* hrate  = (const float*)d_in[10];
    const float* mlr    = (const float*)d_in[11];

    const int H = H_DIM;
    const int B = in_sizes[0] / H;       // 16384
    const int ACT = in_sizes[5];         // 1000

    float* out      = (float*)d_out;
    float* out_w    = out + (size_t)B * H;
    float* out_meta = out_w + (size_t)H * H;
    float* out_hist = out_meta + H;

    const float invB = 1.0f / (float)B;

    static bool attr_done = false;
    if (!attr_done) {
        cudaFuncSetAttribute(gemm_mma, cudaFuncAttributeMaxDynamicSharedMemorySize,
                             GEMM_SMEM);
        attr_done = true;
    }

    // 1) x conversion + transposed partials (r14 exact)
    convert_x<<<dim3(1, SPLITX), 256>>>(x);
    // 2) W scale+transpose + STDP history sums + xmean reduce (one launch)
    prep_small<<<1280, 256>>>(W, meta, pre, post, win, dec, invB);
    // 3) GEMM (+ transposed opart + per-CTA totals)
    dim3 ggrid(H / TN, B / TM);
    gemm_mma<<<ggrid, 256, GEMM_SMEM>>>(out);
    // 4) weights + meta + scalars + hist (reduce folded in)
    weights_meta_kernel<<<(H * H) / 1024, 256>>>(
        W, meta, act, ptr, target, hrate, mlr, win, dec,
        out_w, out_meta, out_hist, ACT, invB);
}

// round 16
// speedup vs baseline: 1.0806x; 1.0806x over previous
#include <cuda_runtime.h>
#include <cuda_fp16.h>
#include <cstdint>

// ---------------------------------------------------------------------------
// SynapticPlasticityModule on GB300 — mma.sync fp16 GEMM (r4 mainloop exact)
// as a persistent-CTA kernel (no wave-tail), r14 pipeline otherwise.
// Outputs (d_out, fp32): [output B*H][new_w H*H][new_meta H][hist ACT]
// ---------------------------------------------------------------------------

#define H_DIM 1024
#define B_DIM 16384
#define HIST_LEN 100
#define SPLITX 256
#define MTILES (B_DIM / 128)                // 128

#define TM 128
#define TN 128
#define KC 64
#define NCHUNK (H_DIM / KC)                 // 16
#define NTILE_N (H_DIM / TN)                // 8
#define NTILES_TOTAL (MTILES * NTILE_N)     // 1024
#define STAGE_BYTES (TM * 128 + TN * 128)   // 32768
#define GEMM_SMEM (2 * STAGE_BYTES)         // 65536

// __device__ scratch — g_xpart / g_opart stored TRANSPOSED [h][i] row-major.
__device__ __half g_xh[(size_t)B_DIM * H_DIM];
__device__ __half g_wh[(size_t)H_DIM * H_DIM];
__device__ float  g_xpart[H_DIM * SPLITX];
__device__ float  g_opart[H_DIM * MTILES];
__device__ float  g_xmean[H_DIM];
__device__ float  g_omean[H_DIM];
__device__ float  g_a[H_DIM];
__device__ float  g_b[H_DIM];

__device__ __forceinline__ uint32_t smem_u32(const void* p) {
    uint32_t a;
    asm("{ .reg .u64 t; cvta.to.shared.u64 t, %1; cvt.u32.u64 %0, t; }"
        : "=r"(a) : "l"(p));
    return a;
}
#define SW128(off) ((off) ^ (((off) >> 3) & 0x70))

#define CP_ASYNC16(smem_addr, gptr) \
    asm volatile("cp.async.cg.shared.global [%0], [%1], 16;" \
                 :: "r"(smem_addr), "l"(gptr) : "memory")
#define CP_COMMIT() asm volatile("cp.async.commit_group;" ::: "memory")
#define CP_WAIT1()  asm volatile("cp.async.wait_group 1;" ::: "memory")
#define CP_WAIT0()  asm volatile("cp.async.wait_group 0;" ::: "memory")

__device__ __forceinline__ void ldmx4(uint32_t* r, uint32_t addr) {
    asm volatile("ldmatrix.sync.aligned.m8n8.x4.shared.b16 {%0,%1,%2,%3}, [%4];"
                 : "=r"(r[0]), "=r"(r[1]), "=r"(r[2]), "=r"(r[3]) : "r"(addr));
}
__device__ __forceinline__ void mma16816(float* d, const uint32_t* a,
                                         const uint32_t* b) {
    asm volatile(
        "mma.sync.aligned.m16n8k16.row.col.f32.f16.f16.f32 "
        "{%0,%1,%2,%3}, {%4,%5,%6,%7}, {%8,%9}, {%0,%1,%2,%3};"
        : "+f"(d[0]), "+f"(d[1]), "+f"(d[2]), "+f"(d[3])
        : "r"(a[0]), "r"(a[1]), "r"(a[2]), "r"(a[3]), "r"(b[0]), "r"(b[1]));
}

// ---------------------------------------------------------------------------
// convert_x (r14 exact): fp32 -> fp16, transposed column partials.
// ---------------------------------------------------------------------------
__global__ __launch_bounds__(256) void convert_x(const float* __restrict__ x)
{
    const int rows_per = B_DIM / SPLITX;     // 64
    const int c4 = threadIdx.x * 4;
    const size_t row0 = (size_t)blockIdx.y * rows_per;

    float4 s = make_float4(0.f, 0.f, 0.f, 0.f);
    const float* p = x + row0 * H_DIM + c4;
    __half* q = g_xh + row0 * H_DIM + c4;

#pragma unroll 4
    for (int r = 0; r < rows_per; r++) {
        float4 v = *reinterpret_cast<const float4*>(p + (size_t)r * H_DIM);
        s.x += v.x; s.y += v.y; s.z += v.z; s.w += v.w;
        __half2 h01 = __floats2half2_rn(v.x, v.y);
        __half2 h23 = __floats2half2_rn(v.z, v.w);
        *reinterpret_cast<uint2*>(q + (size_t)r * H_DIM) =
            make_uint2(*reinterpret_cast<uint32_t*>(&h01),
                       *reinterpret_cast<uint32_t*>(&h23));
    }
    const int blk = blockIdx.y;
    g_xpart[(size_t)(c4 + 0) * SPLITX + blk] = s.x;
    g_xpart[(size_t)(c4 + 1) * SPLITX + blk] = s.y;
    g_xpart[(size_t)(c4 + 2) * SPLITX + blk] = s.z;
    g_xpart[(size_t)(c4 + 3) * SPLITX + blk] = s.w;
}

// ---------------------------------------------------------------------------
// prep_small (r13/r14 exact): [0,1024) convert_w tiles; [1024,1152) STDP sums.
// ---------------------------------------------------------------------------
__global__ __launch_bounds__(256) void prep_small(
    const float* __restrict__ W, const float* __restrict__ meta,
    const float* __restrict__ pre_hist, const float* __restrict__ post_hist,
    const float* __restrict__ d_win, const float* __restrict__ d_dec)
{
    __shared__ float tile[32][33];

    if (blockIdx.x < 1024) {
        const int wb = blockIdx.x;
        const int n0 = (wb & 31) * 32;
        const int k0 = (wb >> 5) * 32;
        const int tx = threadIdx.x & 31;
        const int ty = threadIdx.x >> 5;
#pragma unroll
        for (int i = ty; i < 32; i += 8)
            tile[i][tx] = W[(size_t)(k0 + i) * H_DIM + n0 + tx] * meta[n0 + tx];
        __syncthreads();
#pragma unroll
        for (int i = ty; i < 32; i += 8)
            g_wh[(size_t)(n0 + i) * H_DIM + k0 + tx] = __float2half_rn(tile[tx][i]);
    } else {
        const int wid  = threadIdx.x >> 5;
        const int lane = threadIdx.x & 31;
        const int h = (blockIdx.x - 1024) * 8 + wid;

        const float win = *d_win, dec = *d_dec;

        float a = 0.0f, b = 0.0f;
#pragma unroll
        for (int ii = 0; ii < 4; ii++) {
            int i = ii * 32 + lane;
            if (i < 99) {
                float dt = (float)(HIST_LEN - i) * win;
                float wv = 0.01f * expf(-dt * dec);
                a += wv * pre_hist[(size_t)(i + 1) * H_DIM + h];
                if (i >= 1) b += wv * post_hist[(size_t)(i + 1) * H_DIM + h];
            }
        }
#pragma unroll
        for (int o = 16; o > 0; o >>= 1) {
            a += __shfl_xor_sync(0xffffffffu, a, o);
            b += __shfl_xor_sync(0xffffffffu, b, o);
        }
        if (lane == 0) {
            g_a[h] = a;
            g_b[h] = b;
        }
    }
}

// ---------------------------------------------------------------------------
// GEMM — persistent CTAs: each block loops over tiles t += gridDim.x.
// Mainloop + epilogue bodies are r14-byte-exact; only the tile loop is new.
// ---------------------------------------------------------------------------
__global__ __launch_bounds__(256, 2) void gemm_mma(float* __restrict__ C)
{
    extern __shared__ char smem[];
    const uint32_t sb = smem_u32(smem);
    const int tid  = threadIdx.x;
    const int wid  = tid >> 5;
    const int lane = tid & 31;
    const int m_w = (wid & 3) * 32;
    const int n_w = (wid >> 2) * 64;

    const int lrow = tid >> 3;
    const int lseg = tid & 7;

    const int a_row = m_w + (lane & 15);
    const int a_colb = (lane >> 4) << 4;
    const int b_row = n_w + (lane & 7) + ((lane >> 4) & 1) * 8;
    const int b_colb = ((lane >> 3) & 1) << 4;

    for (int t = blockIdx.x; t < NTILES_TOTAL; t += gridDim.x) {
        const int by = t >> 3;          // m tile 0..127
        const int bx = t & 7;           // n tile 0..7
        const int m0 = by * TM;
        const int n0 = bx * TN;

        float acc[2][8][4];
#pragma unroll
        for (int i = 0; i < 2; i++)
#pragma unroll
            for (int j = 0; j < 8; j++)
#pragma unroll
                for (int q = 0; q < 4; q++) acc[i][j][q] = 0.0f;

        const __half* gA = g_xh + (size_t)(m0 + lrow) * H_DIM + lseg * 8;
        const __half* gB = g_wh + (size_t)(n0 + lrow) * H_DIM + lseg * 8;

#define LOAD_STAGE(c, s) do {                                                  \
    const uint32_t base = sb + (s) * STAGE_BYTES;                              \
    const int koff = (c) * KC;                                                 \
    _Pragma("unroll")                                                          \
    for (int it = 0; it < 4; it++) {                                           \
        int row = it * 32 + lrow;                                              \
        uint32_t off = SW128((uint32_t)(row * 128 + lseg * 16));               \
        CP_ASYNC16(base + off, gA + (size_t)it * 32 * H_DIM + koff);           \
    }                                                                          \
    _Pragma("unroll")                                                          \
    for (int it = 0; it < 4; it++) {                                           \
        int row = it * 32 + lrow;                                              \
        uint32_t off = SW128((uint32_t)(row * 128 + lseg * 16));               \
        CP_ASYNC16(base + TM * 128 + off, gB + (size_t)it * 32 * H_DIM + koff);\
    }                                                                          \
} while (0)

        LOAD_STAGE(0, 0);
        CP_COMMIT();

        for (int c = 0; c < NCHUNK; c++) {
            if (c + 1 < NCHUNK) {
                LOAD_STAGE(c + 1, (c + 1) & 1);
                CP_COMMIT();
                CP_WAIT1();
            } else {
                CP_WAIT0();
            }
            __syncthreads();

            const uint32_t baseA = sb + (c & 1) * STAGE_BYTES;
            const uint32_t baseB = baseA + TM * 128;

#pragma unroll
            for (int ks = 0; ks < KC / 16; ks++) {
                uint32_t a[2][4], b[4][4];
#pragma unroll
                for (int mi = 0; mi < 2; mi++) {
                    uint32_t off = (uint32_t)((a_row + mi * 16) * 128 + ks * 32 + a_colb);
                    ldmx4(a[mi], baseA + SW128(off));
                }
#pragma unroll
                for (int bq = 0; bq < 4; bq++) {
                    uint32_t off = (uint32_t)((b_row + bq * 16) * 128 + ks * 32 + b_colb);
                    ldmx4(b[bq], baseB + SW128(off));
                }
#pragma unroll
                for (int mi = 0; mi < 2; mi++)
#pragma unroll
                    for (int bq = 0; bq < 4; bq++) {
                        mma16816(acc[mi][bq * 2 + 0], a[mi], &b[bq][0]);
                        mma16816(acc[mi][bq * 2 + 1], a[mi], &b[bq][2]);
                    }
            }
            __syncthreads();
        }

        // ---- epilogue 1: store C tile
        const int g = lane >> 2, tig = lane & 3;
#pragma unroll
        for (int mi = 0; mi < 2; mi++) {
            const size_t r0 = (size_t)(m0 + m_w + mi * 16 + g);
#pragma unroll
            for (int ni = 0; ni < 8; ni++) {
                const int col = n0 + n_w + ni * 8 + tig * 2;
                *reinterpret_cast<float2*>(C + r0 * H_DIM + col) =
                    make_float2(acc[mi][ni][0], acc[mi][ni][1]);
                *reinterpret_cast<float2*>(C + (r0 + 8) * H_DIM + col) =
                    make_float2(acc[mi][ni][2], acc[mi][ni][3]);
            }
        }

        // ---- epilogue 2: fused column sums -> g_opart[h][mtile] (transposed)
        float* red = reinterpret_cast<float*>(smem);
#pragma unroll
        for (int ni = 0; ni < 8; ni++) {
            float s0 = acc[0][ni][0] + acc[0][ni][2] + acc[1][ni][0] + acc[1][ni][2];
            float s1 = acc[0][ni][1] + acc[0][ni][3] + acc[1][ni][1] + acc[1][ni][3];
#pragma unroll
            for (int o = 4; o < 32; o <<= 1) {
                s0 += __shfl_xor_sync(0xffffffffu, s0, o);
                s1 += __shfl_xor_sync(0xffffffffu, s1, o);
            }
            if (lane < 4) {
                int col = n_w + ni * 8 + lane * 2;
                red[(wid & 3) * 128 + col]     = s0;
                red[(wid & 3) * 128 + col + 1] = s1;
            }
        }
        __syncthreads();
        if (tid < 128) {
            float s = red[tid] + red[128 + tid] + red[256 + tid] + red[384 + tid];
            g_opart[(size_t)(n0 + tid) * MTILES + by] = s;
        }
        __syncthreads();   // drain red reads before next tile's cp.async writes
#undef LOAD_STAGE
    }
}

// ---------------------------------------------------------------------------
// reduce_means (r14 exact): coalesced — partials are [h][i] row-major.
// ---------------------------------------------------------------------------
__global__ __launch_bounds__(256) void reduce_means(
    const float* __restrict__ d_win, const float* __restrict__ d_dec, float invB)
{
    const int wid  = threadIdx.x >> 5;
    const int lane = threadIdx.x & 31;
    const int h = blockIdx.x * 8 + wid;

    const float4* xp = reinterpret_cast<const float4*>(g_xpart + (size_t)h * SPLITX);
    float4 a0 = xp[lane];
    float4 a1 = xp[lane + 32];
    float sx = (a0.x + a0.y) + (a0.z + a0.w) + (a1.x + a1.y) + (a1.z + a1.w);

    const float4* op = reinterpret_cast<const float4*>(g_opart + (size_t)h * MTILES);
    float4 b0 = op[lane];
    float so = (b0.x + b0.y) + (b0.z + b0.w);

#pragma unroll
    for (int o = 16; o > 0; o >>= 1) {
        sx += __shfl_xor_sync(0xffffffffu, sx, o);
        so += __shfl_xor_sync(0xffffffffu, so, o);
    }

    if (lane == 0) {
        g_xmean[h] = sx * invB;
        float om = so * invB;
        g_omean[h] = om;
        float win = *d_win, dec = *d_dec;
        float w99 = 0.01f * expf(-(1.0f * win) * dec);
        g_b[h] = g_b[h] + w99 * om;
    }
}

// ---------------------------------------------------------------------------
// weights + meta + scalars + hist, one kernel (r8/r14 exact).
// ---------------------------------------------------------------------------
__global__ __launch_bounds__(256) void weights_meta_kernel(
    const float* __restrict__ W, const float* __restrict__ meta,
    const float* __restrict__ act, const int* __restrict__ d_ptr,
    const float* __restrict__ d_target, const float* __restrict__ d_hrate,
    const float* __restrict__ d_mlr,
    float* __restrict__ out_w, float* __restrict__ out_meta,
    float* __restrict__ out_hist, int act_len)
{
    __shared__ float sred[8];
    __shared__ float sbc[2];
    const int tid = threadIdx.x;
    const int wid = tid >> 5;
    const int lane = tid & 31;

    float pm = 0.0f;
#pragma unroll
    for (int i = tid; i < H_DIM; i += 256) pm += g_omean[i];
#pragma unroll
    for (int o = 16; o > 0; o >>= 1) pm += __shfl_xor_sync(0xffffffffu, pm, o);
    if (lane == 0) sred[wid] = pm;
    __syncthreads();
    if (wid == 0) {
        float t = (lane < 8) ? sred[lane] : 0.0f;
#pragma unroll
        for (int o = 4; o > 0; o >>= 1) t += __shfl_xor_sync(0xffffffffu, t, o);
        if (lane == 0) sbc[0] = t / (float)H_DIM;
    }
    __syncthreads();

    float pa = 0.0f;
    for (int i = tid; i < act_len; i += 256) pa += act[i];
#pragma unroll
    for (int o = 16; o > 0; o >>= 1) pa += __shfl_xor_sync(0xffffffffu, pa, o);
    if (lane == 0) sred[wid] = pa;
    __syncthreads();
    if (wid == 0) {
        float t = (lane < 8) ? sred[lane] : 0.0f;
#pragma unroll
        for (int o = 4; o > 0; o >>= 1) t += __shfl_xor_sync(0xffffffffu, t, o);
        if (lane == 0) sbc[1] = t;
    }
    __syncthreads();

    const float m = sbc[0];
    const int ptr = *d_ptr;
    const float hist_mean = (sbc[1] - act[ptr] + m) / (float)act_len;
    const float factor = 1.0f + (*d_hrate) * ((*d_target) - hist_mean);

    if (blockIdx.x == 0) {
        for (int i = tid; i < act_len; i += 256)
            out_hist[i] = (i == ptr) ? m : act[i];
    }

    size_t i4 = (size_t)blockIdx.x * 256 + tid;
    size_t base = i4 * 4;
    int r = (int)(base >> 10);
    int c = (int)(base & (H_DIM - 1));
    float om = g_omean[r], gb = g_b[r];

    float4 w  = *reinterpret_cast<const float4*>(W + base);
    float4 ga = *reinterpret_cast<const float4*>(g_a + c);
    float4 xm = *reinterpret_cast<const float4*>(g_xmean + c);

    float4 v;
    v.x = w.x + om * ga.x - gb * xm.x;
    v.y = w.y + om * ga.y - gb * xm.y;
    v.z = w.z + om * ga.z - gb * xm.z;
    v.w = w.w + om * ga.w - gb * xm.w;
#define CLIP1(t) t = fminf(fmaxf(t, -1.0f), 1.0f)
    CLIP1(v.x); CLIP1(v.y); CLIP1(v.z); CLIP1(v.w);
    v.x *= factor; v.y *= factor; v.z *= factor; v.w *= factor;
    CLIP1(v.x); CLIP1(v.y); CLIP1(v.z); CLIP1(v.w);
#undef CLIP1
    *reinterpret_cast<float4*>(out_w + base) = v;

    if (i4 < H_DIM) {
        float mlr = *d_mlr;
        float mv = meta[i4] + mlr * (g_omean[i4] - meta[i4]);
        out_meta[i4] = fminf(fmaxf(mv, 0.0f), 2.0f);
    }
}

// ---------------------------------------------------------------------------
extern "C" void kernel_launch(void* const* d_in, const int* in_sizes, int n_in,
                              void* d_out, int out_size)
{
    const float* x      = (const float*)d_in[0];
    const float* W      = (const float*)d_in[1];
    const float* meta   = (const float*)d_in[2];
    const float* pre    = (const float*)d_in[3];
    const float* post   = (const float*)d_in[4];
    const float* act    = (const float*)d_in[5];
    const int*   ptr    = (const int*)d_in[6];
    const float* win    = (const float*)d_in[7];
    const float* dec    = (const float*)d_in[8];
    const float* target = (const float*)d_in[9];
    const float* hrate  = (const float*)d_in[10];
    const float* mlr    = (const float*)d_in[11];

    const int H = H_DIM;
    const int B = in_sizes[0] / H;       // 16384
    const int ACT = in_sizes[5];         // 1000

    float* out      = (float*)d_out;
    float* out_w    = out + (size_t)B * H;
    float* out_meta = out_w + (size_t)H * H;
    float* out_hist = out_meta + H;

    const float invB = 1.0f / (float)B;

    static int gemm_grid = 0;
    if (!gemm_grid) {
        cudaFuncSetAttribute(gemm_mma, cudaFuncAttributeMaxDynamicSharedMemorySize,
                             GEMM_SMEM);
        int smc = 148;
        cudaDeviceGetAttribute(&smc, cudaDevAttrMultiProcessorCount, 0);
        gemm_grid = smc * 2;
        if (gemm_grid > NTILES_TOTAL) gemm_grid = NTILES_TOTAL;
    }

    // 1) x conversion + transposed partials (r14 exact)
    convert_x<<<dim3(1, SPLITX), 256>>>(x);
    // 2) W scale+transpose + STDP history sums (r14 exact)
    prep_small<<<1152, 256>>>(W, meta, pre, post, win, dec);
    // 3) persistent GEMM (+ transposed opart)
    gemm_mma<<<gemm_grid, 256, GEMM_SMEM>>>(out);
    // 4) xmean + omean + finish g_b (r14 exact)
    reduce_means<<<H_DIM / 8, 256>>>(win, dec, invB);
    // 5) weights + meta + scalars + hist (r14 exact)
    weights_meta_kernel<<<(H * H) / 1024, 256>>>(
        W, meta, act, ptr, target, hrate, mlr, out_w, out_meta, out_hist, ACT);
}

// round 17
// speedup vs baseline: 1.1022x; 1.0200x over previous
#include <cuda_runtime.h>
#include <cuda_fp16.h>
#include <cstdint>

// ---------------------------------------------------------------------------
// SynapticPlasticityModule on GB300 — r14 config (best measured) with the
// xmean reduce hoisted into prep_small; reduce_means lightened.
// Outputs (d_out, fp32): [output B*H][new_w H*H][new_meta H][hist ACT]
// ---------------------------------------------------------------------------

#define H_DIM 1024
#define B_DIM 16384
#define HIST_LEN 100
#define SPLITX 256
#define MTILES (B_DIM / 128)                // 128

#define TM 128
#define TN 128
#define KC 64
#define NCHUNK (H_DIM / KC)                 // 16
#define STAGE_BYTES (TM * 128 + TN * 128)   // 32768
#define GEMM_SMEM (2 * STAGE_BYTES)         // 65536

// __device__ scratch — g_xpart / g_opart stored TRANSPOSED [h][i] row-major.
__device__ __half g_xh[(size_t)B_DIM * H_DIM];
__device__ __half g_wh[(size_t)H_DIM * H_DIM];
__device__ float  g_xpart[H_DIM * SPLITX];
__device__ float  g_opart[H_DIM * MTILES];
__device__ float  g_xmean[H_DIM];
__device__ float  g_omean[H_DIM];
__device__ float  g_a[H_DIM];
__device__ float  g_b[H_DIM];

__device__ __forceinline__ uint32_t smem_u32(const void* p) {
    uint32_t a;
    asm("{ .reg .u64 t; cvta.to.shared.u64 t, %1; cvt.u32.u64 %0, t; }"
        : "=r"(a) : "l"(p));
    return a;
}
#define SW128(off) ((off) ^ (((off) >> 3) & 0x70))

#define CP_ASYNC16(smem_addr, gptr) \
    asm volatile("cp.async.cg.shared.global [%0], [%1], 16;" \
                 :: "r"(smem_addr), "l"(gptr) : "memory")
#define CP_COMMIT() asm volatile("cp.async.commit_group;" ::: "memory")
#define CP_WAIT1()  asm volatile("cp.async.wait_group 1;" ::: "memory")
#define CP_WAIT0()  asm volatile("cp.async.wait_group 0;" ::: "memory")

__device__ __forceinline__ void ldmx4(uint32_t* r, uint32_t addr) {
    asm volatile("ldmatrix.sync.aligned.m8n8.x4.shared.b16 {%0,%1,%2,%3}, [%4];"
                 : "=r"(r[0]), "=r"(r[1]), "=r"(r[2]), "=r"(r[3]) : "r"(addr));
}
__device__ __forceinline__ void mma16816(float* d, const uint32_t* a,
                                         const uint32_t* b) {
    asm volatile(
        "mma.sync.aligned.m16n8k16.row.col.f32.f16.f16.f32 "
        "{%0,%1,%2,%3}, {%4,%5,%6,%7}, {%8,%9}, {%0,%1,%2,%3};"
        : "+f"(d[0]), "+f"(d[1]), "+f"(d[2]), "+f"(d[3])
        : "r"(a[0]), "r"(a[1]), "r"(a[2]), "r"(a[3]), "r"(b[0]), "r"(b[1]));
}

// ---------------------------------------------------------------------------
// convert_x (r14 exact): fp32 -> fp16, transposed column partials.
// ---------------------------------------------------------------------------
__global__ __launch_bounds__(256) void convert_x(const float* __restrict__ x)
{
    const int rows_per = B_DIM / SPLITX;     // 64
    const int c4 = threadIdx.x * 4;
    const size_t row0 = (size_t)blockIdx.y * rows_per;

    float4 s = make_float4(0.f, 0.f, 0.f, 0.f);
    const float* p = x + row0 * H_DIM + c4;
    __half* q = g_xh + row0 * H_DIM + c4;

#pragma unroll 4
    for (int r = 0; r < rows_per; r++) {
        float4 v = *reinterpret_cast<const float4*>(p + (size_t)r * H_DIM);
        s.x += v.x; s.y += v.y; s.z += v.z; s.w += v.w;
        __half2 h01 = __floats2half2_rn(v.x, v.y);
        __half2 h23 = __floats2half2_rn(v.z, v.w);
        *reinterpret_cast<uint2*>(q + (size_t)r * H_DIM) =
            make_uint2(*reinterpret_cast<uint32_t*>(&h01),
                       *reinterpret_cast<uint32_t*>(&h23));
    }
    const int blk = blockIdx.y;
    g_xpart[(size_t)(c4 + 0) * SPLITX + blk] = s.x;
    g_xpart[(size_t)(c4 + 1) * SPLITX + blk] = s.y;
    g_xpart[(size_t)(c4 + 2) * SPLITX + blk] = s.z;
    g_xpart[(size_t)(c4 + 3) * SPLITX + blk] = s.w;
}

// ---------------------------------------------------------------------------
// prep_small: [0,1024) convert_w tiles; [1024,1152) STDP history sums;
// [1152,1280) xmean reduce (coalesced; xpart ready by stream order).
// ---------------------------------------------------------------------------
__global__ __launch_bounds__(256) void prep_small(
    const float* __restrict__ W, const float* __restrict__ meta,
    const float* __restrict__ pre_hist, const float* __restrict__ post_hist,
    const float* __restrict__ d_win, const float* __restrict__ d_dec, float invB)
{
    __shared__ float tile[32][33];

    if (blockIdx.x < 1024) {
        const int wb = blockIdx.x;
        const int n0 = (wb & 31) * 32;
        const int k0 = (wb >> 5) * 32;
        const int tx = threadIdx.x & 31;
        const int ty = threadIdx.x >> 5;
#pragma unroll
        for (int i = ty; i < 32; i += 8)
            tile[i][tx] = W[(size_t)(k0 + i) * H_DIM + n0 + tx] * meta[n0 + tx];
        __syncthreads();
#pragma unroll
        for (int i = ty; i < 32; i += 8)
            g_wh[(size_t)(n0 + i) * H_DIM + k0 + tx] = __float2half_rn(tile[tx][i]);
    } else if (blockIdx.x < 1152) {
        const int wid  = threadIdx.x >> 5;
        const int lane = threadIdx.x & 31;
        const int h = (blockIdx.x - 1024) * 8 + wid;

        const float win = *d_win, dec = *d_dec;

        float a = 0.0f, b = 0.0f;
#pragma unroll
        for (int ii = 0; ii < 4; ii++) {
            int i = ii * 32 + lane;
            if (i < 99) {
                float dt = (float)(HIST_LEN - i) * win;
                float wv = 0.01f * expf(-dt * dec);
                a += wv * pre_hist[(size_t)(i + 1) * H_DIM + h];
                if (i >= 1) b += wv * post_hist[(size_t)(i + 1) * H_DIM + h];
            }
        }
#pragma unroll
        for (int o = 16; o > 0; o >>= 1) {
            a += __shfl_xor_sync(0xffffffffu, a, o);
            b += __shfl_xor_sync(0xffffffffu, b, o);
        }
        if (lane == 0) {
            g_a[h] = a;
            g_b[h] = b;
        }
    } else {
        const int wid  = threadIdx.x >> 5;
        const int lane = threadIdx.x & 31;
        const int h = (blockIdx.x - 1152) * 8 + wid;

        const float4* xp = reinterpret_cast<const float4*>(g_xpart + (size_t)h * SPLITX);
        float4 a0 = xp[lane];
        float4 a1 = xp[lane + 32];
        float sx = (a0.x + a0.y) + (a0.z + a0.w) + (a1.x + a1.y) + (a1.z + a1.w);
#pragma unroll
        for (int o = 16; o > 0; o >>= 1)
            sx += __shfl_xor_sync(0xffffffffu, sx, o);
        if (lane == 0) g_xmean[h] = sx * invB;
    }
}

// ---------------------------------------------------------------------------
// GEMM (r14 exact): r4 mainloop, transposed opart store.
// ---------------------------------------------------------------------------
__global__ __launch_bounds__(256) void gemm_mma(float* __restrict__ C)
{
    extern __shared__ char smem[];
    const uint32_t sb = smem_u32(smem);
    const int tid  = threadIdx.x;
    const int wid  = tid >> 5;
    const int lane = tid & 31;
    const int m0 = blockIdx.y * TM;
    const int n0 = blockIdx.x * TN;
    const int m_w = (wid & 3) * 32;
    const int n_w = (wid >> 2) * 64;

    float acc[2][8][4];
#pragma unroll
    for (int i = 0; i < 2; i++)
#pragma unroll
        for (int j = 0; j < 8; j++)
#pragma unroll
            for (int q = 0; q < 4; q++) acc[i][j][q] = 0.0f;

    const int lrow = tid >> 3;
    const int lseg = tid & 7;
    const __half* gA = g_xh + (size_t)(m0 + lrow) * H_DIM + lseg * 8;
    const __half* gB = g_wh + (size_t)(n0 + lrow) * H_DIM + lseg * 8;

#define LOAD_STAGE(c, s) do {                                                  \
    const uint32_t base = sb + (s) * STAGE_BYTES;                              \
    const int koff = (c) * KC;                                                 \
    _Pragma("unroll")                                                          \
    for (int it = 0; it < 4; it++) {                                           \
        int row = it * 32 + lrow;                                              \
        uint32_t off = SW128((uint32_t)(row * 128 + lseg * 16));               \
        CP_ASYNC16(base + off, gA + (size_t)it * 32 * H_DIM + koff);           \
    }                                                                          \
    _Pragma("unroll")                                                          \
    for (int it = 0; it < 4; it++) {                                           \
        int row = it * 32 + lrow;                                              \
        uint32_t off = SW128((uint32_t)(row * 128 + lseg * 16));               \
        CP_ASYNC16(base + TM * 128 + off, gB + (size_t)it * 32 * H_DIM + koff);\
    }                                                                          \
} while (0)

    LOAD_STAGE(0, 0);
    CP_COMMIT();

    const int a_row = m_w + (lane & 15);
    const int a_colb = (lane >> 4) << 4;
    const int b_row = n_w + (lane & 7) + ((lane >> 4) & 1) * 8;
    const int b_colb = ((lane >> 3) & 1) << 4;

    for (int c = 0; c < NCHUNK; c++) {
        if (c + 1 < NCHUNK) {
            LOAD_STAGE(c + 1, (c + 1) & 1);
            CP_COMMIT();
            CP_WAIT1();
        } else {
            CP_WAIT0();
        }
        __syncthreads();

        const uint32_t baseA = sb + (c & 1) * STAGE_BYTES;
        const uint32_t baseB = baseA + TM * 128;

#pragma unroll
        for (int ks = 0; ks < KC / 16; ks++) {
            uint32_t a[2][4], b[4][4];
#pragma unroll
            for (int mi = 0; mi < 2; mi++) {
                uint32_t off = (uint32_t)((a_row + mi * 16) * 128 + ks * 32 + a_colb);
                ldmx4(a[mi], baseA + SW128(off));
            }
#pragma unroll
            for (int bq = 0; bq < 4; bq++) {
                uint32_t off = (uint32_t)((b_row + bq * 16) * 128 + ks * 32 + b_colb);
                ldmx4(b[bq], baseB + SW128(off));
            }
#pragma unroll
            for (int mi = 0; mi < 2; mi++)
#pragma unroll
                for (int bq = 0; bq < 4; bq++) {
                    mma16816(acc[mi][bq * 2 + 0], a[mi], &b[bq][0]);
                    mma16816(acc[mi][bq * 2 + 1], a[mi], &b[bq][2]);
                }
        }
        __syncthreads();
    }

    // ---- epilogue 1: store C tile
    const int g = lane >> 2, tig = lane & 3;
#pragma unroll
    for (int mi = 0; mi < 2; mi++) {
        const size_t r0 = (size_t)(m0 + m_w + mi * 16 + g);
#pragma unroll
        for (int ni = 0; ni < 8; ni++) {
            const int col = n0 + n_w + ni * 8 + tig * 2;
            *reinterpret_cast<float2*>(C + r0 * H_DIM + col) =
                make_float2(acc[mi][ni][0], acc[mi][ni][1]);
            *reinterpret_cast<float2*>(C + (r0 + 8) * H_DIM + col) =
                make_float2(acc[mi][ni][2], acc[mi][ni][3]);
        }
    }

    // ---- epilogue 2: fused column sums -> g_opart[h][mtile] (transposed)
    float* red = reinterpret_cast<float*>(smem);
#pragma unroll
    for (int ni = 0; ni < 8; ni++) {
        float s0 = acc[0][ni][0] + acc[0][ni][2] + acc[1][ni][0] + acc[1][ni][2];
        float s1 = acc[0][ni][1] + acc[0][ni][3] + acc[1][ni][1] + acc[1][ni][3];
#pragma unroll
        for (int o = 4; o < 32; o <<= 1) {
            s0 += __shfl_xor_sync(0xffffffffu, s0, o);
            s1 += __shfl_xor_sync(0xffffffffu, s1, o);
        }
        if (lane < 4) {
            int col = n_w + ni * 8 + lane * 2;
            red[(wid & 3) * 128 + col]     = s0;
            red[(wid & 3) * 128 + col + 1] = s1;
        }
    }
    __syncthreads();
    if (tid < 128) {
        float s = red[tid] + red[128 + tid] + red[256 + tid] + red[384 + tid];
        g_opart[(size_t)(n0 + tid) * MTILES + blockIdx.y] = s;
    }
#undef LOAD_STAGE
}

// ---------------------------------------------------------------------------
// reduce_means: omean + finish g_b only (xmean moved to prep_small).
// ---------------------------------------------------------------------------
__global__ __launch_bounds__(256) void reduce_means(
    const float* __restrict__ d_win, const float* __restrict__ d_dec, float invB)
{
    const int wid  = threadIdx.x >> 5;
    const int lane = threadIdx.x & 31;
    const int h = blockIdx.x * 8 + wid;

    const float4* op = reinterpret_cast<const float4*>(g_opart + (size_t)h * MTILES);
    float4 b0 = op[lane];
    float so = (b0.x + b0.y) + (b0.z + b0.w);

#pragma unroll
    for (int o = 16; o > 0; o >>= 1)
        so += __shfl_xor_sync(0xffffffffu, so, o);

    if (lane == 0) {
        float om = so * invB;
        g_omean[h] = om;
        float win = *d_win, dec = *d_dec;
        float w99 = 0.01f * expf(-(1.0f * win) * dec);
        g_b[h] = g_b[h] + w99 * om;
    }
}

// ---------------------------------------------------------------------------
// weights + meta + scalars + hist, one kernel (r8/r14 exact).
// ---------------------------------------------------------------------------
__global__ __launch_bounds__(256) void weights_meta_kernel(
    const float* __restrict__ W, const float* __restrict__ meta,
    const float* __restrict__ act, const int* __restrict__ d_ptr,
    const float* __restrict__ d_target, const float* __restrict__ d_hrate,
    const float* __restrict__ d_mlr,
    float* __restrict__ out_w, float* __restrict__ out_meta,
    float* __restrict__ out_hist, int act_len)
{
    __shared__ float sred[8];
    __shared__ float sbc[2];
    const int tid = threadIdx.x;
    const int wid = tid >> 5;
    const int lane = tid & 31;

    float pm = 0.0f;
#pragma unroll
    for (int i = tid; i < H_DIM; i += 256) pm += g_omean[i];
#pragma unroll
    for (int o = 16; o > 0; o >>= 1) pm += __shfl_xor_sync(0xffffffffu, pm, o);
    if (lane == 0) sred[wid] = pm;
    __syncthreads();
    if (wid == 0) {
        float t = (lane < 8) ? sred[lane] : 0.0f;
#pragma unroll
        for (int o = 4; o > 0; o >>= 1) t += __shfl_xor_sync(0xffffffffu, t, o);
        if (lane == 0) sbc[0] = t / (float)H_DIM;
    }
    __syncthreads();

    float pa = 0.0f;
    for (int i = tid; i < act_len; i += 256) pa += act[i];
#pragma unroll
    for (int o = 16; o > 0; o >>= 1) pa += __shfl_xor_sync(0xffffffffu, pa, o);
    if (lane == 0) sred[wid] = pa;
    __syncthreads();
    if (wid == 0) {
        float t = (lane < 8) ? sred[lane] : 0.0f;
#pragma unroll
        for (int o = 4; o > 0; o >>= 1) t += __shfl_xor_sync(0xffffffffu, t, o);
        if (lane == 0) sbc[1] = t;
    }
    __syncthreads();

    const float m = sbc[0];
    const int ptr = *d_ptr;
    const float hist_mean = (sbc[1] - act[ptr] + m) / (float)act_len;
    const float factor = 1.0f + (*d_hrate) * ((*d_target) - hist_mean);

    if (blockIdx.x == 0) {
        for (int i = tid; i < act_len; i += 256)
            out_hist[i] = (i == ptr) ? m : act[i];
    }

    size_t i4 = (size_t)blockIdx.x * 256 + tid;
    size_t base = i4 * 4;
    int r = (int)(base >> 10);
    int c = (int)(base & (H_DIM - 1));
    float om = g_omean[r], gb = g_b[r];

    float4 w  = *reinterpret_cast<const float4*>(W + base);
    float4 ga = *reinterpret_cast<const float4*>(g_a + c);
    float4 xm = *reinterpret_cast<const float4*>(g_xmean + c);

    float4 v;
    v.x = w.x + om * ga.x - gb * xm.x;
    v.y = w.y + om * ga.y - gb * xm.y;
    v.z = w.z + om * ga.z - gb * xm.z;
    v.w = w.w + om * ga.w - gb * xm.w;
#define CLIP1(t) t = fminf(fmaxf(t, -1.0f), 1.0f)
    CLIP1(v.x); CLIP1(v.y); CLIP1(v.z); CLIP1(v.w);
    v.x *= factor; v.y *= factor; v.z *= factor; v.w *= factor;
    CLIP1(v.x); CLIP1(v.y); CLIP1(v.z); CLIP1(v.w);
#undef CLIP1
    *reinterpret_cast<float4*>(out_w + base) = v;

    if (i4 < H_DIM) {
        float mlr = *d_mlr;
        float mv = meta[i4] + mlr * (g_omean[i4] - meta[i4]);
        out_meta[i4] = fminf(fmaxf(mv, 0.0f), 2.0f);
    }
}

// ---------------------------------------------------------------------------
extern "C" void kernel_launch(void* const* d_in, const int* in_sizes, int n_in,
                              void* d_out, int out_size)
{
    const float* x      = (const float*)d_in[0];
    const float* W      = (const float*)d_in[1];
    const float* meta   = (const float*)d_in[2];
    const float* pre    = (const float*)d_in[3];
    const float* post   = (const float*)d_in[4];
    const float* act    = (const float*)d_in[5];
    const int*   ptr    = (const int*)d_in[6];
    const float* win    = (const float*)d_in[7];
    const float* dec    = (const float*)d_in[8];
    const float* target = (const float*)d_in[9];
    const float* hrate  = (const float*)d_in[10];
    const float* mlr    = (const float*)d_in[11];

    const int H = H_DIM;
    const int B = in_sizes[0] / H;       // 16384
    const int ACT = in_sizes[5];         // 1000

    float* out      = (float*)d_out;
    float* out_w    = out + (size_t)B * H;
    float* out_meta = out_w + (size_t)H * H;
    float* out_hist = out_meta + H;

    const float invB = 1.0f / (float)B;

    static bool attr_done = false;
    if (!attr_done) {
        cudaFuncSetAttribute(gemm_mma, cudaFuncAttributeMaxDynamicSharedMemorySize,
                             GEMM_SMEM);
        attr_done = true;
    }

    // 1) x conversion + transposed partials (r14 exact)
    convert_x<<<dim3(1, SPLITX), 256>>>(x);
    // 2) W scale+transpose + STDP history sums + xmean reduce (one launch)
    prep_small<<<1280, 256>>>(W, meta, pre, post, win, dec, invB);
    // 3) GEMM (+ transposed opart) (r14 exact)
    dim3 ggrid(H / TN, B / TM);
    gemm_mma<<<ggrid, 256, GEMM_SMEM>>>(out);
    // 4) omean + finish g_b (lightened)
    reduce_means<<<H_DIM / 8, 256>>>(win, dec, invB);
    // 5) weights + meta + scalars + hist (r14 exact)
    weights_meta_kernel<<<(H * H) / 1024, 256>>>(
        W, meta, act, ptr, target, hrate, mlr, out_w, out_meta, out_hist, ACT);
}